// round 9
// baseline (speedup 1.0000x reference)
#include <cuda_runtime.h>

#define EPS 1e-8f
typedef unsigned long long ull;

constexpr int RS = 1184;                 // img row stride (floats), ≡0 mod 32
// img addr: r*RS + 4*(r/6) + k + 4*(k/32)

constexpr int OFF_BUF0 = 42624;          // chunk buffer 0 (5952 floats); ATT overlays (stride 1476)
constexpr int OFF_BUF1 = 48576;          // chunk buffer 1 (5952 floats); A2 overlays (stride 1440)
constexpr int OFF_ATT  = OFF_BUF0;
constexpr int OFF_A2   = OFF_BUF1;
constexpr int OFF_COS  = OFF_BUF0;       // ci*1320 + l*33 + nbl (ATT dead by then)
constexpr int OFF_W1   = 54528;
constexpr int OFF_B1   = OFF_W1 + 256;
constexpr int OFF_W2S  = OFF_B1 + 8;
constexpr int OFF_B2S  = OFF_W2S + 8;
constexpr int OFF_RED  = OFF_B2S + 4;
constexpr int SMEM_FLOATS = OFF_RED + 160;
constexpr int SMEM_BYTES  = SMEM_FLOATS * 4;   // ~220 KB

__device__ __forceinline__ ull dup2(float a) {
    ull r; asm("mov.b64 %0, {%1, %1};" : "=l"(r) : "f"(a)); return r;
}
__device__ __forceinline__ void f2(ull& d, ull a, ull b) {
    asm("fma.rn.f32x2 %0, %1, %2, %0;" : "+l"(d) : "l"(a), "l"(b));
}
__device__ __forceinline__ void up(ull v, float& lo, float& hi) {
    asm("mov.b64 {%0, %1}, %2;" : "=f"(lo), "=f"(hi) : "l"(v));
}

__global__ __launch_bounds__(384, 1)
void tg_kernel(const float* __restrict__ images, const float* __restrict__ captions,
               const int* __restrict__ cap_lens, const float* __restrict__ rare,
               const float* __restrict__ v1, const float* __restrict__ g1, const float* __restrict__ b1,
               const float* __restrict__ v2, const float* __restrict__ g2, const float* __restrict__ b2,
               const int* __restrict__ lam_p, float* __restrict__ out)
{
    extern __shared__ float sm[];
    const int tid = threadIdx.x;
    const int img = blockIdx.x;
    const int c0  = blockIdx.y * 4;

    // ---- preamble: image -> SMEM, RS=1184 + per-6-row-block skew + per-32-k skew ----
    {
        const float4* g4 = (const float4*)(images + (size_t)img * 36 * 1024);
        for (int i = tid; i < 9216; i += 384) {
            int r = i >> 8, kf = (i & 255) * 4;
            *(float4*)(sm + r * RS + 4 * (r / 6) + kf + 4 * (kf >> 5)) = g4[i];
        }
    }
    if (tid < 8) {
        int j = tid; float s = 0.f;
        for (int n = 0; n < 32; n++) { float v = v1[j * 32 + n]; s += v * v; }
        float inv = g1[j] / sqrtf(s);
        for (int n = 0; n < 32; n++) sm[OFF_W1 + j * 32 + n] = v1[j * 32 + n] * inv;
        sm[OFF_B1 + j] = b1[j];
    }
    if (tid == 8) {
        float w2s[8] = {0,0,0,0,0,0,0,0}; float b2s = 0.f;
        for (int k = 0; k < 6; k++) {
            float s = 0.f;
            for (int j = 0; j < 8; j++) { float v = v2[k * 8 + j]; s += v * v; }
            float inv = g2[k] / sqrtf(s);
            for (int j = 0; j < 8; j++) w2s[j] += v2[k * 8 + j] * inv;
            b2s += b2[k];
        }
        for (int j = 0; j < 8; j++) sm[OFF_W2S + j] = w2s[j];
        sm[OFF_B2S] = b2s;
    }
    const float lam = (float)(*lam_p);

    // Phase A map: khalf x [lg (slow) x capi x rg (fast)]
    const int khalf = tid / 192, t2 = tid % 192;
    const int lg = t2 / 24, r3 = t2 % 24, capi = r3 / 6, rg = r3 % 6;
    const int mylen = cap_lens[c0 + capi];
    const bool actA = (lg * 5 < mylen);

    ull acc[6][5];
    #pragma unroll
    for (int q = 0; q < 6; q++)
        #pragma unroll
        for (int j = 0; j < 5; j++) acc[q][j] = 0ull;

    // caption chunk prefetch (1280 float4 / 384 thr)
    float4 pf0, pf1, pf2, pf3;
    const int i0 = tid, i1 = tid + 384, i2 = tid + 768, i3 = tid + 1152;

    #define PF_LOAD(REG, I, KC) if ((I) < 1280) { \
        int ci_ = (I) / 320, r2_ = (I) % 320, l_ = r2_ >> 3, k4_ = r2_ & 7; \
        REG = *(const float4*)(captions + (((size_t)(c0 + ci_) * 40 + l_) << 10) + (KC) * 32 + k4_ * 4); }
    #define PF_STORE(REG, I, BASE) if ((I) < 1280) { \
        int ci_ = (I) / 320, r2_ = (I) % 320, l_ = r2_ >> 3, k4_ = r2_ & 7; \
        *(float4*)(sm + (BASE) + ci_ * 1448 + l_ * 36 + k4_ * 4) = REG; }

    const float* ibase = sm + rg * (6 * RS) + 4 * rg + khalf * 16;
    const float* cbase0 = sm + OFF_BUF0 + capi * 1448 + lg * 5 * 36 + khalf * 16;
    const float* cbase1 = cbase0 + (OFF_BUF1 - OFF_BUF0);

    // prologue: chunk0 -> buf0, prefetch chunk1
    PF_LOAD(pf0, i0, 0) PF_LOAD(pf1, i1, 0) PF_LOAD(pf2, i2, 0) PF_LOAD(pf3, i3, 0)
    PF_STORE(pf0, i0, OFF_BUF0) PF_STORE(pf1, i1, OFF_BUF0)
    PF_STORE(pf2, i2, OFF_BUF0) PF_STORE(pf3, i3, OFF_BUF0)
    PF_LOAD(pf0, i0, 1) PF_LOAD(pf1, i1, 1) PF_LOAD(pf2, i2, 1) PF_LOAD(pf3, i3, 1)
    __syncthreads();   // img + buf0 ready

    // ================= Phase A: S = img . cap^T (double-buffered, 1 sync/iter) =============
    for (int kc = 0; kc < 32; kc++) {
        const int dstBase = (kc & 1) ? OFF_BUF0 : OFF_BUF1;   // chunk kc+1 goes to other buffer
        if (kc + 1 < 32) {
            PF_STORE(pf0, i0, dstBase) PF_STORE(pf1, i1, dstBase)
            PF_STORE(pf2, i2, dstBase) PF_STORE(pf3, i3, dstBase)
        }
        if (kc + 2 < 32) {
            PF_LOAD(pf0, i0, kc + 2) PF_LOAD(pf1, i1, kc + 2)
            PF_LOAD(pf2, i2, kc + 2) PF_LOAD(pf3, i3, kc + 2)
        }
        if (actA) {
            const float* ib = ibase + kc * 36;
            const float* cb = (kc & 1) ? cbase1 : cbase0;
            #pragma unroll
            for (int k4 = 0; k4 < 16; k4 += 4) {
                ulonglong2 I[6], C[5];
                #pragma unroll
                for (int q = 0; q < 6; q++) I[q] = *(const ulonglong2*)(ib + q * RS + k4);
                #pragma unroll
                for (int j = 0; j < 5; j++) C[j] = *(const ulonglong2*)(cb + j * 36 + k4);
                #pragma unroll
                for (int q = 0; q < 6; q++)
                    #pragma unroll
                    for (int j = 0; j < 5; j++) {
                        f2(acc[q][j], I[q].x, C[j].x);
                        f2(acc[q][j], I[q].y, C[j].y);
                    }
            }
        }
        __syncthreads();
    }

    // ---- epilogue: khalf reduction through ATT, leaky-relu + mask ----
    {
        float* base = sm + OFF_ATT + capi * 1476;
        if (khalf) {
            #pragma unroll
            for (int q = 0; q < 6; q++)
                #pragma unroll
                for (int j = 0; j < 5; j++) {
                    float lo, hi; up(acc[q][j], lo, hi);
                    base[(rg * 6 + q) * 41 + lg * 5 + j] = lo + hi;
                }
        }
        __syncthreads();
        if (!khalf) {
            #pragma unroll
            for (int q = 0; q < 6; q++)
                #pragma unroll
                for (int j = 0; j < 5; j++) {
                    float lo, hi; up(acc[q][j], lo, hi);
                    int w = lg * 5 + j;
                    float v = lo + hi + base[(rg * 6 + q) * 41 + w];
                    v = (v > 0.f ? v : 0.1f * v);
                    base[(rg * 6 + q) * 41 + w] = (w < mylen) ? v : 0.f;
                }
        }
    }
    __syncthreads();

    // ===== B1: l2 norm over words per region (288 thr, shfl pair-reduce) =====
    if (tid < 288) {
        int ci = tid / 72, rr = (tid % 72) >> 1, half = tid & 1;
        float* row = sm + OFF_ATT + ci * 1476 + rr * 41 + half * 20;
        float s = 0.f;
        #pragma unroll
        for (int l = 0; l < 20; l++) { float v = row[l]; s += v * v; }
        float so = __shfl_xor_sync(0xffffffffu, s, 1);
        float inv = 1.f / (sqrtf(s + so) + EPS);
        #pragma unroll
        for (int l = 0; l < 20; l++) row[l] *= inv;
    }
    __syncthreads();

    // ===== B2: softmax over regions -> A2[ci][r*40+l] at OFF_A2 (stride 1440) =====
    if (tid < 160) {
        int ci = tid / 40, l = tid % 40;
        int len = cap_lens[c0 + ci];
        float* A2 = sm + OFF_A2 + ci * 1440;
        if (l < len) {
            const float* Sb = sm + OFF_ATT + ci * 1476;
            float e[36]; float ssum = 0.f;
            #pragma unroll
            for (int r = 0; r < 36; r++) { e[r] = __expf(Sb[r * 41 + l] * lam); ssum += e[r]; }
            float inv = 1.f / ssum;
            #pragma unroll
            for (int r = 0; r < 36; r++) A2[r * 40 + l] = e[r] * inv;
        } else {
            #pragma unroll
            for (int r = 0; r < 36; r++) A2[r * 40 + l] = 0.f;
        }
    }
    __syncthreads();

    // ===== Phase C: per-warp (ci, 8-word octet), lane = nbl, dim-quarters =====
    {
        const int warp = tid >> 5, nbl = tid & 31;
        #pragma unroll 1
        for (int g = warp; g < 20; g += 12) {
            const int ci = g / 5, wg8 = g % 5;
            const int w0 = wg8 * 8;
            const int len = cap_lens[c0 + ci];
            if (w0 >= len) continue;
            const float* A2b = sm + OFF_A2 + ci * 1440 + w0;
            const float* capg = captions + (((size_t)(c0 + ci) * 40 + w0) << 10);
            float W12[8], CN[8], QN[8];
            #pragma unroll
            for (int w = 0; w < 8; w++) { W12[w] = 0.f; CN[w] = 0.f; QN[w] = 0.f; }
            #pragma unroll 1
            for (int hq = 0; hq < 4; hq++) {
                ull wc[8][4];
                #pragma unroll
                for (int w = 0; w < 8; w++)
                    #pragma unroll
                    for (int e = 0; e < 4; e++) wc[w][e] = 0ull;
                #pragma unroll 1
                for (int rb = 0; rb < 6; rb++) {
                    const float* imgb = sm + rb * (6 * RS) + 4 * rb + nbl * 36 + hq * 8;
                    const float* a2b = A2b + rb * 240;
                    #pragma unroll
                    for (int q = 0; q < 6; q++) {
                        float4 a0 = *(const float4*)(a2b + q * 40);
                        float4 a1 = *(const float4*)(a2b + q * 40 + 4);
                        ulonglong2 v01 = *(const ulonglong2*)(imgb + q * RS);
                        ulonglong2 v23 = *(const ulonglong2*)(imgb + q * RS + 4);
                        #define CW(W, AV) { ull d_ = dup2(AV); \
                            f2(wc[W][0], d_, v01.x); f2(wc[W][1], d_, v01.y); \
                            f2(wc[W][2], d_, v23.x); f2(wc[W][3], d_, v23.y); }
                        CW(0, a0.x) CW(1, a0.y) CW(2, a0.z) CW(3, a0.w)
                        CW(4, a1.x) CW(5, a1.y) CW(6, a1.z) CW(7, a1.w)
                        #undef CW
                    }
                }
                #pragma unroll
                for (int w = 0; w < 8; w++) {
                    const float* qp = capg + w * 1024 + nbl * 32 + hq * 8;
                    float4 qa = *(const float4*)qp;
                    float4 qb = *(const float4*)(qp + 4);
                    float lo, hi;
                    up(wc[w][0], lo, hi); W12[w] += lo * qa.x + hi * qa.y; CN[w] += lo * lo + hi * hi; QN[w] += qa.x * qa.x + qa.y * qa.y;
                    up(wc[w][1], lo, hi); W12[w] += lo * qa.z + hi * qa.w; CN[w] += lo * lo + hi * hi; QN[w] += qa.z * qa.z + qa.w * qa.w;
                    up(wc[w][2], lo, hi); W12[w] += lo * qb.x + hi * qb.y; CN[w] += lo * lo + hi * hi; QN[w] += qb.x * qb.x + qb.y * qb.y;
                    up(wc[w][3], lo, hi); W12[w] += lo * qb.z + hi * qb.w; CN[w] += lo * lo + hi * hi; QN[w] += qb.z * qb.z + qb.w * qb.w;
                }
            }
            #pragma unroll
            for (int w = 0; w < 8; w++)
                sm[OFF_COS + ci * 1320 + (w0 + w) * 33 + nbl] =
                    W12[w] / fmaxf(sqrtf(CN[w]) * sqrtf(QN[w]), EPS);
        }
    }
    __syncthreads();

    // ===== Phase D: weight-normed MLP + masked mean =====
    if (tid < 160) {
        int ci = tid / 40, l = tid % 40;
        int len = cap_lens[c0 + ci];
        float res = 0.f;
        if (l < len) {
            const float* rr = rare + ((size_t)(c0 + ci) * 40 + l) * 32;
            const float* cb = sm + OFF_COS + ci * 1320 + l * 33;
            float x[32];
            #pragma unroll
            for (int n = 0; n < 32; n++) x[n] = cb[n] + 0.4f * rr[n];
            float persum = sm[OFF_B2S];
            #pragma unroll
            for (int j = 0; j < 8; j++) {
                float hsum = sm[OFF_B1 + j];
                const float* wr = sm + OFF_W1 + j * 32;
                #pragma unroll
                for (int n = 0; n < 32; n++) hsum = fmaf(x[n], wr[n], hsum);
                float hc = fminf(fmaxf(hsum, -15.f), 15.f);
                float t = __expf(2.f * hc);
                float th = __fdividef(t - 1.f, t + 1.f);
                persum = fmaf(th, sm[OFF_W2S + j], persum);
            }
            res = persum;
        }
        sm[OFF_RED + tid] = res;
    }
    __syncthreads();
    if (tid < 4) {
        int len = cap_lens[c0 + tid];
        float s = 0.f;
        for (int l = 0; l < len; l++) s += sm[OFF_RED + tid * 40 + l];
        out[(size_t)img * 64 + (c0 + tid)] = s / (float)(len * 6);
    }
}

extern "C" void kernel_launch(void* const* d_in, const int* in_sizes, int n_in,
                              void* d_out, int out_size) {
    const float* images   = (const float*)d_in[0];
    const float* captions = (const float*)d_in[1];
    const int*   cap_lens = (const int*)d_in[2];
    const float* rare     = (const float*)d_in[3];
    const float* v1       = (const float*)d_in[4];
    const float* g1       = (const float*)d_in[5];
    const float* b1       = (const float*)d_in[6];
    const float* v2       = (const float*)d_in[7];
    const float* g2       = (const float*)d_in[8];
    const float* b2       = (const float*)d_in[9];
    const int*   lam      = (const int*)d_in[12];
    float* out = (float*)d_out;

    cudaFuncSetAttribute(tg_kernel, cudaFuncAttributeMaxDynamicSharedMemorySize, SMEM_BYTES);
    tg_kernel<<<dim3(64, 16, 1), 384, SMEM_BYTES>>>(
        images, captions, cap_lens, rare, v1, g1, b1, v2, g2, b2, lam, out);
}